// round 10
// baseline (speedup 1.0000x reference)
#include <cuda_runtime.h>
#include <math_constants.h>

#define BB 64
#define TT 4096
#define QDIM 1024
#define ADIM 256
#define MASK_VAL (-1e30f)

// Scratch (allocation-free rule: device globals)
__device__ float g_pq[BB * ADIM];        // processed query (B, AD)
__device__ float g_energies[BB * TT];    // masked energies (B, T)

__device__ __forceinline__ float tanh_fast(float x) {
    float y;
    asm("tanh.approx.f32 %0, %1;" : "=f"(y) : "f"(x));
    return y;
}

// ---------------------------------------------------------------------------
// Kernel 1: pq[b,d] = dot(query[b,:], Wq[d,:])   (64 x 256, K=1024)
// Tile (8 b x 8 d), grid = 256 blocks. Warp w owns one Wq row in registers
// and accumulates all 8 b-rows concurrently (ILP=8). Frozen this round.
// ---------------------------------------------------------------------------
#define PQ_BT 8
__global__ void __launch_bounds__(256) pq_kernel(const float* __restrict__ query,
                                                 const float* __restrict__ Wq) {
    __shared__ float sq[PQ_BT * QDIM];             // 32 KB

    const int lane = threadIdx.x & 31;
    const int warp = threadIdx.x >> 5;             // 0..7
    const int btile = blockIdx.x >> 5;             // 0..7
    const int dtile = blockIdx.x & 31;             // 0..31
    const int b0 = btile * PQ_BT;
    const int d  = dtile * 8 + warp;

    const float4* w4 = reinterpret_cast<const float4*>(Wq + (size_t)d * QDIM);
    float4 w[8];
#pragma unroll
    for (int k = 0; k < 8; ++k) w[k] = w4[lane + 32 * k];

    {
        const float4* qg = reinterpret_cast<const float4*>(query + (size_t)b0 * QDIM);
        float4* sq4 = reinterpret_cast<float4*>(sq);
#pragma unroll
        for (int i = 0; i < 8; ++i)
            sq4[threadIdx.x + 256 * i] = qg[threadIdx.x + 256 * i];
    }
    __syncthreads();

    const float4* sq4 = reinterpret_cast<const float4*>(sq);
    float s[PQ_BT];
#pragma unroll
    for (int bi = 0; bi < PQ_BT; ++bi) s[bi] = 0.f;

#pragma unroll
    for (int k = 0; k < 8; ++k) {
#pragma unroll
        for (int bi = 0; bi < PQ_BT; ++bi) {
            float4 a = sq4[bi * 256 + lane + 32 * k];
            s[bi] += a.x * w[k].x + a.y * w[k].y + a.z * w[k].z + a.w * w[k].w;
        }
    }

#pragma unroll
    for (int off = 16; off > 0; off >>= 1) {
#pragma unroll
        for (int bi = 0; bi < PQ_BT; ++bi)
            s[bi] += __shfl_xor_sync(0xffffffffu, s[bi], off);
    }
    if (lane == 0) {
#pragma unroll
        for (int bi = 0; bi < PQ_BT; ++bi)
            g_pq[(b0 + bi) * ADIM + d] = s[bi];
    }
}

// ---------------------------------------------------------------------------
// Kernel 2: energies[b,t] = sum_d tanh(pq[b,d] + pm[b,t,d]) * v[d]; mask.
// One warp per 16 t-rows; masked rows (~50%) never touch pm.
// DEPTH-2 software pipeline: TWO row-pairs in flight (8-12 outstanding
// LDG.128/warp at steady state). Two explicit register slot-sets, body
// duplicated via macro -> no runtime-indexed arrays, no local memory.
// pm read with __ldcs (streaming, read-once).
// mask arrives as int32 (harness normalizes bool -> int32).
// ---------------------------------------------------------------------------
#define TPW 16           // t-rows per warp

#define K2_LOADPAIR(S, IT)                                                    \
    {                                                                         \
        const int jn_ = (IT) * 2;                                             \
        pi0_##S = __fns(bits, 0, jn_ + 1);                                    \
        hs_##S = (jn_ + 1 < n);                                               \
        pi1_##S = hs_##S ? __fns(bits, 0, jn_ + 2) : pi0_##S;                 \
        const float4* y0_ = reinterpret_cast<const float4*>(                  \
            pm + (base + pi0_##S) * ADIM);                                    \
        const float4* y1_ = reinterpret_cast<const float4*>(                  \
            pm + (base + pi1_##S) * ADIM);                                    \
        a0_##S = __ldcs(y0_ + lane);  c0_##S = __ldcs(y0_ + lane + 32);       \
        a1_##S = __ldcs(y1_ + lane);  c1_##S = __ldcs(y1_ + lane + 32);       \
    }

#define K2_BODY(S)                                                            \
    {                                                                         \
        const int ci0 = pi0_##S, ci1 = pi1_##S;                               \
        const bool chas1 = hs_##S;                                            \
        const float4 A0 = a0_##S, C0 = c0_##S, A1 = a1_##S, C1 = c1_##S;      \
        if (it + 2 < nIter) {                                                 \
            K2_LOADPAIR(S, it + 2)                                            \
        }                                                                     \
        float s0, s1;                                                         \
        s0  = tanh_fast(A0.x + p0.x) * v0.x;                                  \
        s1  = tanh_fast(A1.x + p0.x) * v0.x;                                  \
        s0 += tanh_fast(A0.y + p0.y) * v0.y;                                  \
        s1 += tanh_fast(A1.y + p0.y) * v0.y;                                  \
        s0 += tanh_fast(A0.z + p0.z) * v0.z;                                  \
        s1 += tanh_fast(A1.z + p0.z) * v0.z;                                  \
        s0 += tanh_fast(A0.w + p0.w) * v0.w;                                  \
        s1 += tanh_fast(A1.w + p0.w) * v0.w;                                  \
        s0 += tanh_fast(C0.x + p1.x) * v1.x;                                  \
        s1 += tanh_fast(C1.x + p1.x) * v1.x;                                  \
        s0 += tanh_fast(C0.y + p1.y) * v1.y;                                  \
        s1 += tanh_fast(C1.y + p1.y) * v1.y;                                  \
        s0 += tanh_fast(C0.z + p1.z) * v1.z;                                  \
        s1 += tanh_fast(C1.z + p1.z) * v1.z;                                  \
        s0 += tanh_fast(C0.w + p1.w) * v1.w;                                  \
        s1 += tanh_fast(C1.w + p1.w) * v1.w;                                  \
        _Pragma("unroll")                                                     \
        for (int off = 16; off > 0; off >>= 1) {                              \
            s0 += __shfl_xor_sync(0xffffffffu, s0, off);                      \
            s1 += __shfl_xor_sync(0xffffffffu, s1, off);                      \
        }                                                                     \
        if (lane == 0) {                                                      \
            g_energies[base + ci0] = s0;                                      \
            if (chas1) g_energies[base + ci1] = s1;                           \
        }                                                                     \
    }

__global__ void __launch_bounds__(256) energies_kernel(
        const float* __restrict__ pm,
        const int* __restrict__ mask,
        const float* __restrict__ v) {
    const int lane = threadIdx.x & 31;
    const int warp = threadIdx.x >> 5;
    const int gw = blockIdx.x * 8 + warp;          // global warp id
    const int warpsPerB = TT / TPW;                // 256
    const int b = gw / warpsPerB;
    const int t0 = (gw % warpsPerB) * TPW;
    const size_t base = (size_t)b * TT + t0;

    // Mask for the 16 rows: lanes 0..15 load one each.
    const int myMask = (lane < TPW) ? mask[base + lane] : 1;
    const unsigned bits = __ballot_sync(0xffffffffu, (lane < TPW) && (myMask == 0));

    // Masked rows: write MASK_VAL upfront, coalesced.
    if (lane < TPW && myMask)
        g_energies[base + lane] = MASK_VAL;

    const int n = __popc(bits);
    if (n == 0) return;

    // Register-resident pq row and v (8 floats each per lane)
    const float4* pq4 = reinterpret_cast<const float4*>(g_pq + b * ADIM);
    const float4* v4 = reinterpret_cast<const float4*>(v);
    const float4 p0 = pq4[lane], p1 = pq4[lane + 32];
    const float4 v0 = v4[lane], v1 = v4[lane + 32];

    const int nIter = (n + 1) >> 1;

    // Pipeline slots
    int pi0_0, pi1_0, pi0_1 = 0, pi1_1 = 0;
    bool hs_0, hs_1 = false;
    float4 a0_0, c0_0, a1_0, c1_0;
    float4 a0_1, c0_1, a1_1, c1_1;
    a0_1 = c0_1 = a1_1 = c1_1 = make_float4(0.f, 0.f, 0.f, 0.f);

    // Prologue: pairs 0 and 1 in flight.
    K2_LOADPAIR(0, 0)
    if (nIter > 1) {
        K2_LOADPAIR(1, 1)
    }

    int it = 0;
    for (;;) {
        K2_BODY(0)
        if (++it >= nIter) break;
        K2_BODY(1)
        if (++it >= nIter) break;
    }
}

// ---------------------------------------------------------------------------
// Kernel 3: row softmax over T=4096. One block (1024 thr) per batch row.
// Single-pass: |energies| <= sum|v| ~ 13 so __expf cannot overflow, and
// masked -1e30 underflows to exactly 0 (softmax shift-invariance).
// ---------------------------------------------------------------------------
__global__ void __launch_bounds__(1024) softmax_kernel(float* __restrict__ out) {
    const int b = blockIdx.x;
    const int tid = threadIdx.x;
    const int lane = tid & 31;
    const int warp = tid >> 5;
    __shared__ float red[32];
    __shared__ float bcast;

    float e[4];
    float s = 0.f;
#pragma unroll
    for (int i = 0; i < 4; ++i) {
        e[i] = __expf(g_energies[(size_t)b * TT + i * 1024 + tid]);
        s += e[i];
    }
#pragma unroll
    for (int off = 16; off > 0; off >>= 1)
        s += __shfl_xor_sync(0xffffffffu, s, off);
    if (lane == 0) red[warp] = s;
    __syncthreads();
    if (warp == 0) {
        float ss = red[lane];
#pragma unroll
        for (int off = 16; off > 0; off >>= 1)
            ss += __shfl_xor_sync(0xffffffffu, ss, off);
        if (lane == 0) bcast = ss;
    }
    __syncthreads();
    const float inv = 1.0f / bcast;

#pragma unroll
    for (int i = 0; i < 4; ++i)
        out[(size_t)b * TT + i * 1024 + tid] = e[i] * inv;
}

// ---------------------------------------------------------------------------
extern "C" void kernel_launch(void* const* d_in, const int* in_sizes, int n_in,
                              void* d_out, int out_size) {
    const float* query = (const float*)d_in[0];          // (64, 1024) f32
    const float* pm    = (const float*)d_in[1];          // (64, 4096, 256) f32
    const int*   mask  = (const int*)d_in[2];            // (64, 4096) bool -> int32
    const float* Wq    = (const float*)d_in[3];          // (256, 1024) f32
    const float* v     = (const float*)d_in[4];          // (256,) f32
    float* out = (float*)d_out;                          // (64, 4096) f32

    // K1: (8 b-tiles) x (32 d-tiles) = 256 blocks, 256 threads
    pq_kernel<<<256, 256>>>(query, Wq);
    // K2: 64*4096/16 warps / 8 per block = 2048 blocks
    energies_kernel<<<2048, 256>>>(pm, mask, v);
    // K3: one block per batch row
    softmax_kernel<<<BB, 1024>>>(out);
}

// round 11
// speedup vs baseline: 1.2416x; 1.2416x over previous
#include <cuda_runtime.h>
#include <math_constants.h>

#define BB 64
#define TT 4096
#define QDIM 1024
#define ADIM 256
#define MASK_VAL (-1e30f)

// Scratch (allocation-free rule: device globals)
__device__ float g_pq[BB * ADIM];        // processed query (B, AD)
__device__ float g_energies[BB * TT];    // masked energies (B, T)

__device__ __forceinline__ float tanh_fast(float x) {
    float y;
    asm("tanh.approx.f32 %0, %1;" : "=f"(y) : "f"(x));
    return y;
}

// ---------------------------------------------------------------------------
// Kernel 1: pq[b,d] = dot(query[b,:], Wq[d,:])   (64 x 256, K=1024)
// k1 runs COLD every graph replay (k2's 135 MB stream thrashes L2), so it is
// latency-bound. Tile (4 b x 8 d), grid = 16 x 32 = 512 blocks, 16 KB smem,
// ~60 regs -> ALL blocks co-resident (4+/SM) -> total time ~ one block's
// latency instead of 2 serial waves of heavy blocks.
// Per-(b,d) summation order identical to prior rounds (same float4 split,
// same shfl tree) -> bit-identical results.
// ---------------------------------------------------------------------------
#define PQ_BT 4
__global__ void __launch_bounds__(256) pq_kernel(const float* __restrict__ query,
                                                 const float* __restrict__ Wq) {
    __shared__ float sq[PQ_BT * QDIM];             // 16 KB

    const int lane = threadIdx.x & 31;
    const int warp = threadIdx.x >> 5;             // 0..7
    const int btile = blockIdx.x >> 5;             // 0..15
    const int dtile = blockIdx.x & 31;             // 0..31
    const int b0 = btile * PQ_BT;
    const int d  = dtile * 8 + warp;

    // Wq row for this warp (8 float4 per lane), issued first.
    const float4* w4 = reinterpret_cast<const float4*>(Wq + (size_t)d * QDIM);
    float4 w[8];
#pragma unroll
    for (int k = 0; k < 8; ++k) w[k] = w4[lane + 32 * k];

    // Cooperative load of query tile: 1024 float4 / 256 thr = 4 each.
    {
        const float4* qg = reinterpret_cast<const float4*>(query + (size_t)b0 * QDIM);
        float4* sq4 = reinterpret_cast<float4*>(sq);
#pragma unroll
        for (int i = 0; i < 4; ++i)
            sq4[threadIdx.x + 256 * i] = qg[threadIdx.x + 256 * i];
    }
    __syncthreads();

    const float4* sq4 = reinterpret_cast<const float4*>(sq);
    float s[PQ_BT];
#pragma unroll
    for (int bi = 0; bi < PQ_BT; ++bi) s[bi] = 0.f;

#pragma unroll
    for (int k = 0; k < 8; ++k) {
#pragma unroll
        for (int bi = 0; bi < PQ_BT; ++bi) {
            float4 a = sq4[bi * 256 + lane + 32 * k];
            s[bi] += a.x * w[k].x + a.y * w[k].y + a.z * w[k].z + a.w * w[k].w;
        }
    }

#pragma unroll
    for (int off = 16; off > 0; off >>= 1) {
#pragma unroll
        for (int bi = 0; bi < PQ_BT; ++bi)
            s[bi] += __shfl_xor_sync(0xffffffffu, s[bi], off);
    }
    if (lane == 0) {
#pragma unroll
        for (int bi = 0; bi < PQ_BT; ++bi)
            g_pq[(b0 + bi) * ADIM + d] = s[bi];
    }
}

// ---------------------------------------------------------------------------
// Kernel 2: energies[b,t] = sum_d tanh(pq[b,d] + pm[b,t,d]) * v[d]; mask.
// EXACT R7 structure (best measured): one warp per 16 t-rows, masked rows
// (~50%) never touch pm, two rows per iteration, DEPTH-1 software pipeline
// (depth-2 in R10 blew up registers and collapsed occupancy -> 47 us).
// pm read with __ldcs (streaming, read-once).
// mask arrives as int32 (harness normalizes bool -> int32).
// ---------------------------------------------------------------------------
#define TPW 16           // t-rows per warp
__global__ void __launch_bounds__(256) energies_kernel(
        const float* __restrict__ pm,
        const int* __restrict__ mask,
        const float* __restrict__ v) {
    const int lane = threadIdx.x & 31;
    const int warp = threadIdx.x >> 5;
    const int gw = blockIdx.x * 8 + warp;          // global warp id
    const int warpsPerB = TT / TPW;                // 256
    const int b = gw / warpsPerB;
    const int t0 = (gw % warpsPerB) * TPW;
    const size_t base = (size_t)b * TT + t0;

    // Mask for the 16 rows: lanes 0..15 load one each.
    const int myMask = (lane < TPW) ? mask[base + lane] : 1;
    const unsigned bits = __ballot_sync(0xffffffffu, (lane < TPW) && (myMask == 0));

    // Masked rows: write MASK_VAL upfront, coalesced.
    if (lane < TPW && myMask)
        g_energies[base + lane] = MASK_VAL;

    const int n = __popc(bits);
    if (n == 0) return;

    // Register-resident pq row and v (8 floats each per lane)
    const float4* pq4 = reinterpret_cast<const float4*>(g_pq + b * ADIM);
    const float4* v4 = reinterpret_cast<const float4*>(v);
    const float4 p0 = pq4[lane], p1 = pq4[lane + 32];
    const float4 v0 = v4[lane], v1 = v4[lane + 32];

    const int nIter = (n + 1) >> 1;

    // Prologue: issue loads for iteration 0.
    int i0 = __fns(bits, 0, 1);
    int i1 = (n > 1) ? __fns(bits, 0, 2) : i0;
    const float4* x0 = reinterpret_cast<const float4*>(pm + (base + i0) * ADIM);
    const float4* x1 = reinterpret_cast<const float4*>(pm + (base + i1) * ADIM);
    float4 a0 = __ldcs(x0 + lane);
    float4 c0 = __ldcs(x0 + lane + 32);
    float4 a1 = __ldcs(x1 + lane);
    float4 c1 = __ldcs(x1 + lane + 32);

    for (int it = 0; it < nIter; ++it) {
        const int j = it * 2;
        const bool has1 = (j + 1 < n);
        const int ci0 = i0, ci1 = i1;
        const float4 A0 = a0, C0 = c0, A1 = a1, C1 = c1;

        // Prefetch next pair before the reduce chain of the current pair.
        if (it + 1 < nIter) {
            const int jn = j + 2;
            i0 = __fns(bits, 0, jn + 1);
            i1 = (jn + 1 < n) ? __fns(bits, 0, jn + 2) : i0;
            const float4* y0 = reinterpret_cast<const float4*>(pm + (base + i0) * ADIM);
            const float4* y1 = reinterpret_cast<const float4*>(pm + (base + i1) * ADIM);
            a0 = __ldcs(y0 + lane);
            c0 = __ldcs(y0 + lane + 32);
            a1 = __ldcs(y1 + lane);
            c1 = __ldcs(y1 + lane + 32);
        }

        float s0, s1;
        s0  = tanh_fast(A0.x + p0.x) * v0.x;
        s1  = tanh_fast(A1.x + p0.x) * v0.x;
        s0 += tanh_fast(A0.y + p0.y) * v0.y;
        s1 += tanh_fast(A1.y + p0.y) * v0.y;
        s0 += tanh_fast(A0.z + p0.z) * v0.z;
        s1 += tanh_fast(A1.z + p0.z) * v0.z;
        s0 += tanh_fast(A0.w + p0.w) * v0.w;
        s1 += tanh_fast(A1.w + p0.w) * v0.w;
        s0 += tanh_fast(C0.x + p1.x) * v1.x;
        s1 += tanh_fast(C1.x + p1.x) * v1.x;
        s0 += tanh_fast(C0.y + p1.y) * v1.y;
        s1 += tanh_fast(C1.y + p1.y) * v1.y;
        s0 += tanh_fast(C0.z + p1.z) * v1.z;
        s1 += tanh_fast(C1.z + p1.z) * v1.z;
        s0 += tanh_fast(C0.w + p1.w) * v1.w;
        s1 += tanh_fast(C1.w + p1.w) * v1.w;

#pragma unroll
        for (int off = 16; off > 0; off >>= 1) {
            s0 += __shfl_xor_sync(0xffffffffu, s0, off);
            s1 += __shfl_xor_sync(0xffffffffu, s1, off);
        }

        if (lane == 0) {
            g_energies[base + ci0] = s0;
            if (has1) g_energies[base + ci1] = s1;
        }
    }
}

// ---------------------------------------------------------------------------
// Kernel 3: row softmax over T=4096. One block (1024 thr) per batch row.
// Single-pass: |energies| <= sum|v| ~ 13 so __expf cannot overflow, and
// masked -1e30 underflows to exactly 0 (softmax shift-invariance).
// ---------------------------------------------------------------------------
__global__ void __launch_bounds__(1024) softmax_kernel(float* __restrict__ out) {
    const int b = blockIdx.x;
    const int tid = threadIdx.x;
    const int lane = tid & 31;
    const int warp = tid >> 5;
    __shared__ float red[32];
    __shared__ float bcast;

    float e[4];
    float s = 0.f;
#pragma unroll
    for (int i = 0; i < 4; ++i) {
        e[i] = __expf(g_energies[(size_t)b * TT + i * 1024 + tid]);
        s += e[i];
    }
#pragma unroll
    for (int off = 16; off > 0; off >>= 1)
        s += __shfl_xor_sync(0xffffffffu, s, off);
    if (lane == 0) red[warp] = s;
    __syncthreads();
    if (warp == 0) {
        float ss = red[lane];
#pragma unroll
        for (int off = 16; off > 0; off >>= 1)
            ss += __shfl_xor_sync(0xffffffffu, ss, off);
        if (lane == 0) bcast = ss;
    }
    __syncthreads();
    const float inv = 1.0f / bcast;

#pragma unroll
    for (int i = 0; i < 4; ++i)
        out[(size_t)b * TT + i * 1024 + tid] = e[i] * inv;
}

// ---------------------------------------------------------------------------
extern "C" void kernel_launch(void* const* d_in, const int* in_sizes, int n_in,
                              void* d_out, int out_size) {
    const float* query = (const float*)d_in[0];          // (64, 1024) f32
    const float* pm    = (const float*)d_in[1];          // (64, 4096, 256) f32
    const int*   mask  = (const int*)d_in[2];            // (64, 4096) bool -> int32
    const float* Wq    = (const float*)d_in[3];          // (256, 1024) f32
    const float* v     = (const float*)d_in[4];          // (256,) f32
    float* out = (float*)d_out;                          // (64, 4096) f32

    // K1: (16 b-tiles) x (32 d-tiles) = 512 blocks, 256 threads
    pq_kernel<<<512, 256>>>(query, Wq);
    // K2: 64*4096/16 warps / 8 per block = 2048 blocks
    energies_kernel<<<2048, 256>>>(pm, mask, v);
    // K3: one block per batch row
    softmax_kernel<<<BB, 1024>>>(out);
}

// round 12
// speedup vs baseline: 1.2500x; 1.0068x over previous
#include <cuda_runtime.h>
#include <math_constants.h>

#define BB 64
#define TT 4096
#define QDIM 1024
#define ADIM 256
#define MASK_VAL (-1e30f)

// Scratch (allocation-free rule: device globals)
__device__ float g_pq[BB * ADIM];        // processed query (B, AD)
__device__ float g_energies[BB * TT];    // masked energies (B, T)

__device__ __forceinline__ float tanh_fast(float x) {
    float y;
    asm("tanh.approx.f32 %0, %1;" : "=f"(y) : "f"(x));
    return y;
}

// ---------------------------------------------------------------------------
// Kernel 1: pq[b,d] = dot(query[b,:], Wq[d,:])   (64 x 256, K=1024)
// Tile (4 b x 8 d), 512 blocks, all co-resident. Frozen (R11 showed total
// time is insensitive to k1 shape; in-graph it costs ~2-3 us).
// ---------------------------------------------------------------------------
#define PQ_BT 4
__global__ void __launch_bounds__(256) pq_kernel(const float* __restrict__ query,
                                                 const float* __restrict__ Wq) {
    __shared__ float sq[PQ_BT * QDIM];             // 16 KB

    const int lane = threadIdx.x & 31;
    const int warp = threadIdx.x >> 5;             // 0..7
    const int btile = blockIdx.x >> 5;             // 0..15
    const int dtile = blockIdx.x & 31;             // 0..31
    const int b0 = btile * PQ_BT;
    const int d  = dtile * 8 + warp;

    const float4* w4 = reinterpret_cast<const float4*>(Wq + (size_t)d * QDIM);
    float4 w[8];
#pragma unroll
    for (int k = 0; k < 8; ++k) w[k] = w4[lane + 32 * k];

    {
        const float4* qg = reinterpret_cast<const float4*>(query + (size_t)b0 * QDIM);
        float4* sq4 = reinterpret_cast<float4*>(sq);
#pragma unroll
        for (int i = 0; i < 4; ++i)
            sq4[threadIdx.x + 256 * i] = qg[threadIdx.x + 256 * i];
    }
    __syncthreads();

    const float4* sq4 = reinterpret_cast<const float4*>(sq);
    float s[PQ_BT];
#pragma unroll
    for (int bi = 0; bi < PQ_BT; ++bi) s[bi] = 0.f;

#pragma unroll
    for (int k = 0; k < 8; ++k) {
#pragma unroll
        for (int bi = 0; bi < PQ_BT; ++bi) {
            float4 a = sq4[bi * 256 + lane + 32 * k];
            s[bi] += a.x * w[k].x + a.y * w[k].y + a.z * w[k].z + a.w * w[k].w;
        }
    }

#pragma unroll
    for (int off = 16; off > 0; off >>= 1) {
#pragma unroll
        for (int bi = 0; bi < PQ_BT; ++bi)
            s[bi] += __shfl_xor_sync(0xffffffffu, s[bi], off);
    }
    if (lane == 0) {
#pragma unroll
        for (int bi = 0; bi < PQ_BT; ++bi)
            g_pq[(b0 + bi) * ADIM + d] = s[bi];
    }
}

// ---------------------------------------------------------------------------
// Kernel 2: energies[b,t] = sum_d tanh(pq[b,d] + pm[b,t,d]) * v[d]; mask.
// R7 structure (best measured) + PDL: launched with programmatic stream
// serialization; everything that does NOT depend on g_pq (mask phase, v
// preload, prologue pm loads) runs BEFORE cudaGridDependencySynchronize(),
// overlapping k1's execution and the inter-kernel gap. g_pq is read only
// after the sync.
// pm read with __ldcs (streaming); mask arrives as int32.
// ---------------------------------------------------------------------------
#define TPW 16           // t-rows per warp
__global__ void __launch_bounds__(256) energies_kernel(
        const float* __restrict__ pm,
        const int* __restrict__ mask,
        const float* __restrict__ v) {
    const int lane = threadIdx.x & 31;
    const int warp = threadIdx.x >> 5;
    const int gw = blockIdx.x * 8 + warp;          // global warp id
    const int warpsPerB = TT / TPW;                // 256
    const int b = gw / warpsPerB;
    const int t0 = (gw % warpsPerB) * TPW;
    const size_t base = (size_t)b * TT + t0;

    // ---- Phase A: independent of k1's output ----
    const int myMask = (lane < TPW) ? mask[base + lane] : 1;
    const unsigned bits = __ballot_sync(0xffffffffu, (lane < TPW) && (myMask == 0));

    if (lane < TPW && myMask)
        g_energies[base + lane] = MASK_VAL;

    const int n = __popc(bits);
    if (n == 0) {
        cudaGridDependencySynchronize();           // still must not exit early
        return;
    }

    const float4* v4 = reinterpret_cast<const float4*>(v);
    const float4 v0 = v4[lane], v1 = v4[lane + 32];

    const int nIter = (n + 1) >> 1;

    // Prologue pm loads (indices depend only on mask).
    int i0 = __fns(bits, 0, 1);
    int i1 = (n > 1) ? __fns(bits, 0, 2) : i0;
    const float4* x0 = reinterpret_cast<const float4*>(pm + (base + i0) * ADIM);
    const float4* x1 = reinterpret_cast<const float4*>(pm + (base + i1) * ADIM);
    float4 a0 = __ldcs(x0 + lane);
    float4 c0 = __ldcs(x0 + lane + 32);
    float4 a1 = __ldcs(x1 + lane);
    float4 c1 = __ldcs(x1 + lane + 32);

    // ---- Wait for k1 (g_pq) ----
    cudaGridDependencySynchronize();

    const float4* pq4 = reinterpret_cast<const float4*>(g_pq + b * ADIM);
    const float4 p0 = pq4[lane], p1 = pq4[lane + 32];

    for (int it = 0; it < nIter; ++it) {
        const int j = it * 2;
        const bool has1 = (j + 1 < n);
        const int ci0 = i0, ci1 = i1;
        const float4 A0 = a0, C0 = c0, A1 = a1, C1 = c1;

        // Prefetch next pair before the reduce chain of the current pair.
        if (it + 1 < nIter) {
            const int jn = j + 2;
            i0 = __fns(bits, 0, jn + 1);
            i1 = (jn + 1 < n) ? __fns(bits, 0, jn + 2) : i0;
            const float4* y0 = reinterpret_cast<const float4*>(pm + (base + i0) * ADIM);
            const float4* y1 = reinterpret_cast<const float4*>(pm + (base + i1) * ADIM);
            a0 = __ldcs(y0 + lane);
            c0 = __ldcs(y0 + lane + 32);
            a1 = __ldcs(y1 + lane);
            c1 = __ldcs(y1 + lane + 32);
        }

        float s0, s1;
        s0  = tanh_fast(A0.x + p0.x) * v0.x;
        s1  = tanh_fast(A1.x + p0.x) * v0.x;
        s0 += tanh_fast(A0.y + p0.y) * v0.y;
        s1 += tanh_fast(A1.y + p0.y) * v0.y;
        s0 += tanh_fast(A0.z + p0.z) * v0.z;
        s1 += tanh_fast(A1.z + p0.z) * v0.z;
        s0 += tanh_fast(A0.w + p0.w) * v0.w;
        s1 += tanh_fast(A1.w + p0.w) * v0.w;
        s0 += tanh_fast(C0.x + p1.x) * v1.x;
        s1 += tanh_fast(C1.x + p1.x) * v1.x;
        s0 += tanh_fast(C0.y + p1.y) * v1.y;
        s1 += tanh_fast(C1.y + p1.y) * v1.y;
        s0 += tanh_fast(C0.z + p1.z) * v1.z;
        s1 += tanh_fast(C1.z + p1.z) * v1.z;
        s0 += tanh_fast(C0.w + p1.w) * v1.w;
        s1 += tanh_fast(C1.w + p1.w) * v1.w;

#pragma unroll
        for (int off = 16; off > 0; off >>= 1) {
            s0 += __shfl_xor_sync(0xffffffffu, s0, off);
            s1 += __shfl_xor_sync(0xffffffffu, s1, off);
        }

        if (lane == 0) {
            g_energies[base + ci0] = s0;
            if (has1) g_energies[base + ci1] = s1;
        }
    }
}

// ---------------------------------------------------------------------------
// Kernel 3: row softmax over T=4096. One block (1024 thr) per batch row.
// Single-pass (shift-free): energies bounded, masked -1e30 -> exp = 0.
// ---------------------------------------------------------------------------
__global__ void __launch_bounds__(1024) softmax_kernel(float* __restrict__ out) {
    const int b = blockIdx.x;
    const int tid = threadIdx.x;
    const int lane = tid & 31;
    const int warp = tid >> 5;
    __shared__ float red[32];
    __shared__ float bcast;

    float e[4];
    float s = 0.f;
#pragma unroll
    for (int i = 0; i < 4; ++i) {
        e[i] = __expf(g_energies[(size_t)b * TT + i * 1024 + tid]);
        s += e[i];
    }
#pragma unroll
    for (int off = 16; off > 0; off >>= 1)
        s += __shfl_xor_sync(0xffffffffu, s, off);
    if (lane == 0) red[warp] = s;
    __syncthreads();
    if (warp == 0) {
        float ss = red[lane];
#pragma unroll
        for (int off = 16; off > 0; off >>= 1)
            ss += __shfl_xor_sync(0xffffffffu, ss, off);
        if (lane == 0) bcast = ss;
    }
    __syncthreads();
    const float inv = 1.0f / bcast;

#pragma unroll
    for (int i = 0; i < 4; ++i)
        out[(size_t)b * TT + i * 1024 + tid] = e[i] * inv;
}

// ---------------------------------------------------------------------------
extern "C" void kernel_launch(void* const* d_in, const int* in_sizes, int n_in,
                              void* d_out, int out_size) {
    const float* query = (const float*)d_in[0];          // (64, 1024) f32
    const float* pm    = (const float*)d_in[1];          // (64, 4096, 256) f32
    const int*   mask  = (const int*)d_in[2];            // (64, 4096) bool -> int32
    const float* Wq    = (const float*)d_in[3];          // (256, 1024) f32
    const float* v     = (const float*)d_in[4];          // (256,) f32
    float* out = (float*)d_out;                          // (64, 4096) f32

    // K1: 512 blocks, 256 threads
    pq_kernel<<<512, 256>>>(query, Wq);

    // K2 with PDL: overlaps its g_pq-independent preamble with k1.
    {
        cudaLaunchConfig_t cfg = {};
        cfg.gridDim = dim3(2048);
        cfg.blockDim = dim3(256);
        cfg.dynamicSmemBytes = 0;
        cfg.stream = 0;                            // capture (legacy) stream
        cudaLaunchAttribute attrs[1];
        attrs[0].id = cudaLaunchAttributeProgrammaticStreamSerialization;
        attrs[0].val.programmaticStreamSerializationAllowed = 1;
        cfg.attrs = attrs;
        cfg.numAttrs = 1;
        cudaLaunchKernelEx(&cfg, energies_kernel, pm, mask, v);
    }

    // K3: one block per batch row
    softmax_kernel<<<BB, 1024>>>(out);
}

// round 13
// speedup vs baseline: 1.2586x; 1.0068x over previous
#include <cuda_runtime.h>
#include <math_constants.h>

#define BB 64
#define TT 4096
#define QDIM 1024
#define ADIM 256
#define MASK_VAL (-1e30f)

// Scratch (allocation-free rule: device globals)
__device__ float g_pq[BB * ADIM];        // processed query (B, AD)
__device__ float g_energies[BB * TT];    // masked energies (B, T)

__device__ __forceinline__ float tanh_fast(float x) {
    float y;
    asm("tanh.approx.f32 %0, %1;" : "=f"(y) : "f"(x));
    return y;
}

// ---------------------------------------------------------------------------
// Kernel 1: pq[b,d] = dot(query[b,:], Wq[d,:])   (64 x 256, K=1024)
// Tile (4 b x 8 d), 512 blocks, all co-resident. Frozen.
// ---------------------------------------------------------------------------
#define PQ_BT 4
__global__ void __launch_bounds__(256) pq_kernel(const float* __restrict__ query,
                                                 const float* __restrict__ Wq) {
    __shared__ float sq[PQ_BT * QDIM];             // 16 KB

    const int lane = threadIdx.x & 31;
    const int warp = threadIdx.x >> 5;             // 0..7
    const int btile = blockIdx.x >> 5;             // 0..15
    const int dtile = blockIdx.x & 31;             // 0..31
    const int b0 = btile * PQ_BT;
    const int d  = dtile * 8 + warp;

    const float4* w4 = reinterpret_cast<const float4*>(Wq + (size_t)d * QDIM);
    float4 w[8];
#pragma unroll
    for (int k = 0; k < 8; ++k) w[k] = w4[lane + 32 * k];

    {
        const float4* qg = reinterpret_cast<const float4*>(query + (size_t)b0 * QDIM);
        float4* sq4 = reinterpret_cast<float4*>(sq);
#pragma unroll
        for (int i = 0; i < 4; ++i)
            sq4[threadIdx.x + 256 * i] = qg[threadIdx.x + 256 * i];
    }
    __syncthreads();

    const float4* sq4 = reinterpret_cast<const float4*>(sq);
    float s[PQ_BT];
#pragma unroll
    for (int bi = 0; bi < PQ_BT; ++bi) s[bi] = 0.f;

#pragma unroll
    for (int k = 0; k < 8; ++k) {
#pragma unroll
        for (int bi = 0; bi < PQ_BT; ++bi) {
            float4 a = sq4[bi * 256 + lane + 32 * k];
            s[bi] += a.x * w[k].x + a.y * w[k].y + a.z * w[k].z + a.w * w[k].w;
        }
    }

#pragma unroll
    for (int off = 16; off > 0; off >>= 1) {
#pragma unroll
        for (int bi = 0; bi < PQ_BT; ++bi)
            s[bi] += __shfl_xor_sync(0xffffffffu, s[bi], off);
    }
    if (lane == 0) {
#pragma unroll
        for (int bi = 0; bi < PQ_BT; ++bi)
            g_pq[(b0 + bi) * ADIM + d] = s[bi];
    }
}

// ---------------------------------------------------------------------------
// Kernel 2: energies[b,t] = sum_d tanh(pq[b,d] + pm[b,t,d]) * v[d]; mask.
// R7 structure + PDL. NEW: __launch_bounds__(256, 4) caps regs at 64 ->
// 4 blocks/SM = 32 warps/SM. Little's law: need ~25 KB in flight per SM
// (42 B/cyc x ~600 cyc); 16 warps x 8 LDG.128 gave only 16 KB (-> 4.2 TB/s,
// the measured plateau); 32 warps give 32 KB -> BW-bound.
// pm read with __ldcs (streaming); mask arrives as int32.
// ---------------------------------------------------------------------------
#define TPW 16           // t-rows per warp
__global__ void __launch_bounds__(256, 4) energies_kernel(
        const float* __restrict__ pm,
        const int* __restrict__ mask,
        const float* __restrict__ v) {
    const int lane = threadIdx.x & 31;
    const int warp = threadIdx.x >> 5;
    const int gw = blockIdx.x * 8 + warp;          // global warp id
    const int warpsPerB = TT / TPW;                // 256
    const int b = gw / warpsPerB;
    const int t0 = (gw % warpsPerB) * TPW;
    const size_t base = (size_t)b * TT + t0;

    // ---- Phase A: independent of k1's output ----
    const int myMask = (lane < TPW) ? mask[base + lane] : 1;
    const unsigned bits = __ballot_sync(0xffffffffu, (lane < TPW) && (myMask == 0));

    if (lane < TPW && myMask)
        g_energies[base + lane] = MASK_VAL;

    const int n = __popc(bits);
    if (n == 0) {
        cudaGridDependencySynchronize();
        return;
    }

    const float4* v4 = reinterpret_cast<const float4*>(v);
    const float4 v0 = v4[lane], v1 = v4[lane + 32];

    const int nIter = (n + 1) >> 1;

    // Prologue pm loads (indices depend only on mask).
    int i0 = __fns(bits, 0, 1);
    int i1 = (n > 1) ? __fns(bits, 0, 2) : i0;
    const float4* x0 = reinterpret_cast<const float4*>(pm + (base + i0) * ADIM);
    const float4* x1 = reinterpret_cast<const float4*>(pm + (base + i1) * ADIM);
    float4 a0 = __ldcs(x0 + lane);
    float4 c0 = __ldcs(x0 + lane + 32);
    float4 a1 = __ldcs(x1 + lane);
    float4 c1 = __ldcs(x1 + lane + 32);

    // ---- Wait for k1 (g_pq) ----
    cudaGridDependencySynchronize();

    const float4* pq4 = reinterpret_cast<const float4*>(g_pq + b * ADIM);
    const float4 p0 = pq4[lane], p1 = pq4[lane + 32];

    for (int it = 0; it < nIter; ++it) {
        const int j = it * 2;
        const bool has1 = (j + 1 < n);
        const int ci0 = i0, ci1 = i1;
        const float4 A0 = a0, C0 = c0, A1 = a1, C1 = c1;

        // Prefetch next pair before the reduce chain of the current pair.
        if (it + 1 < nIter) {
            const int jn = j + 2;
            i0 = __fns(bits, 0, jn + 1);
            i1 = (jn + 1 < n) ? __fns(bits, 0, jn + 2) : i0;
            const float4* y0 = reinterpret_cast<const float4*>(pm + (base + i0) * ADIM);
            const float4* y1 = reinterpret_cast<const float4*>(pm + (base + i1) * ADIM);
            a0 = __ldcs(y0 + lane);
            c0 = __ldcs(y0 + lane + 32);
            a1 = __ldcs(y1 + lane);
            c1 = __ldcs(y1 + lane + 32);
        }

        float s0, s1;
        s0  = tanh_fast(A0.x + p0.x) * v0.x;
        s1  = tanh_fast(A1.x + p0.x) * v0.x;
        s0 += tanh_fast(A0.y + p0.y) * v0.y;
        s1 += tanh_fast(A1.y + p0.y) * v0.y;
        s0 += tanh_fast(A0.z + p0.z) * v0.z;
        s1 += tanh_fast(A1.z + p0.z) * v0.z;
        s0 += tanh_fast(A0.w + p0.w) * v0.w;
        s1 += tanh_fast(A1.w + p0.w) * v0.w;
        s0 += tanh_fast(C0.x + p1.x) * v1.x;
        s1 += tanh_fast(C1.x + p1.x) * v1.x;
        s0 += tanh_fast(C0.y + p1.y) * v1.y;
        s1 += tanh_fast(C1.y + p1.y) * v1.y;
        s0 += tanh_fast(C0.z + p1.z) * v1.z;
        s1 += tanh_fast(C1.z + p1.z) * v1.z;
        s0 += tanh_fast(C0.w + p1.w) * v1.w;
        s1 += tanh_fast(C1.w + p1.w) * v1.w;

#pragma unroll
        for (int off = 16; off > 0; off >>= 1) {
            s0 += __shfl_xor_sync(0xffffffffu, s0, off);
            s1 += __shfl_xor_sync(0xffffffffu, s1, off);
        }

        if (lane == 0) {
            g_energies[base + ci0] = s0;
            if (has1) g_energies[base + ci1] = s1;
        }
    }
}

// ---------------------------------------------------------------------------
// Kernel 3: row softmax over T=4096. One block (1024 thr) per batch row.
// Single-pass (shift-free): energies bounded, masked -1e30 -> exp = 0.
// ---------------------------------------------------------------------------
__global__ void __launch_bounds__(1024) softmax_kernel(float* __restrict__ out) {
    const int b = blockIdx.x;
    const int tid = threadIdx.x;
    const int lane = tid & 31;
    const int warp = tid >> 5;
    __shared__ float red[32];
    __shared__ float bcast;

    float e[4];
    float s = 0.f;
#pragma unroll
    for (int i = 0; i < 4; ++i) {
        e[i] = __expf(g_energies[(size_t)b * TT + i * 1024 + tid]);
        s += e[i];
    }
#pragma unroll
    for (int off = 16; off > 0; off >>= 1)
        s += __shfl_xor_sync(0xffffffffu, s, off);
    if (lane == 0) red[warp] = s;
    __syncthreads();
    if (warp == 0) {
        float ss = red[lane];
#pragma unroll
        for (int off = 16; off > 0; off >>= 1)
            ss += __shfl_xor_sync(0xffffffffu, ss, off);
        if (lane == 0) bcast = ss;
    }
    __syncthreads();
    const float inv = 1.0f / bcast;

#pragma unroll
    for (int i = 0; i < 4; ++i)
        out[(size_t)b * TT + i * 1024 + tid] = e[i] * inv;
}

// ---------------------------------------------------------------------------
extern "C" void kernel_launch(void* const* d_in, const int* in_sizes, int n_in,
                              void* d_out, int out_size) {
    const float* query = (const float*)d_in[0];          // (64, 1024) f32
    const float* pm    = (const float*)d_in[1];          // (64, 4096, 256) f32
    const int*   mask  = (const int*)d_in[2];            // (64, 4096) bool -> int32
    const float* Wq    = (const float*)d_in[3];          // (256, 1024) f32
    const float* v     = (const float*)d_in[4];          // (256,) f32
    float* out = (float*)d_out;                          // (64, 4096) f32

    // K1: 512 blocks, 256 threads
    pq_kernel<<<512, 256>>>(query, Wq);

    // K2 with PDL (neutral but harmless; kept for comparability).
    {
        cudaLaunchConfig_t cfg = {};
        cfg.gridDim = dim3(2048);
        cfg.blockDim = dim3(256);
        cfg.dynamicSmemBytes = 0;
        cfg.stream = 0;
        cudaLaunchAttribute attrs[1];
        attrs[0].id = cudaLaunchAttributeProgrammaticStreamSerialization;
        attrs[0].val.programmaticStreamSerializationAllowed = 1;
        cfg.attrs = attrs;
        cfg.numAttrs = 1;
        cudaLaunchKernelEx(&cfg, energies_kernel, pm, mask, v);
    }

    // K3: one block per batch row
    softmax_kernel<<<BB, 1024>>>(out);
}